// round 1
// baseline (speedup 1.0000x reference)
#include <cuda_runtime.h>
#include <cuda_bf16.h>
#include <mma.h>

using namespace nvcuda;

// Problem dims (fixed by the dataset)
#define N_TOK   8192        // B*S = 4*2048
#define D_IN    2048
#define D_OUT   8192

// Tiling
#define BM      128
#define BN      64
#define BK      32
#define A_LD    36          // 32 + 4 pad (floats)
#define B_LD    36
#define C_LD    68          // 64 + 4 pad

#define GEMM_SMEM_FLOATS  (BM*A_LD + 2*BN*B_LD)          // 9216
#define EPI_SMEM_FLOATS   (2*BM*C_LD)                    // 17408
#define SMEM_BYTES        (EPI_SMEM_FLOATS * 4)          // 69632 (> gemm part)

// Scratch for keys = mu_weight * softplus(sigma_weight)  (64 MB, device global: no allocs)
__device__ float g_keys[(size_t)D_OUT * D_IN];

__device__ __forceinline__ float to_tf32(float x) {
    asm("cvt.rna.tf32.f32 %0, %0;" : "+f"(x));
    return x;
}

// ---------------------------------------------------------------------------
// prep: keys[o,d] = mu[o,d] * softplus(sigma[o,d])
// ---------------------------------------------------------------------------
__global__ void prep_keys_kernel(const float* __restrict__ mu,
                                 const float* __restrict__ sigma,
                                 float* __restrict__ keys,
                                 int n) {
    int i = blockIdx.x * blockDim.x + threadIdx.x;
    int stride = gridDim.x * blockDim.x;
    for (; i < n; i += stride) {
        float s = sigma[i];
        float sp = (s > 20.0f) ? s : log1pf(expf(s));
        keys[i] = mu[i] * sp;
    }
}

// ---------------------------------------------------------------------------
// Fused dual GEMM + epilogue.
//   scores[m,o] = (x[m,:] . keys[o,:]) / sqrt(D_IN)
//   lin[m,o]    =  x[m,:] . mu[o,:]
//   out[m,o]    = relu(scores - gate[o]) * lin + bias[o]
// CTA tile: 128 x 64, 8 warps in 4(M) x 2(N), warp tile 32x32 per matrix.
// ---------------------------------------------------------------------------
__global__ void __launch_bounds__(256)
sbl_gemm_kernel(const float* __restrict__ x,
                const float* __restrict__ keys,
                const float* __restrict__ mu,
                const float* __restrict__ gate,
                const float* __restrict__ bias,
                float* __restrict__ o_final,
                float* __restrict__ o_scores,
                float* __restrict__ o_output) {
    extern __shared__ float smem[];
    float* As = smem;                  // [BM][A_LD]
    float* Bk = smem + BM * A_LD;      // [BN][B_LD]
    float* Bm = Bk + BN * B_LD;        // [BN][B_LD]

    const int tid = threadIdx.x;
    const int warp = tid >> 5;
    const int wm = warp & 3;           // 0..3  -> M offset wm*32
    const int wn = warp >> 2;          // 0..1  -> N offset wn*32

    const int m_base = blockIdx.y * BM;
    const int n_base = blockIdx.x * BN;

    wmma::fragment<wmma::accumulator, 16, 16, 8, float> acc_s[2][2], acc_l[2][2];
    #pragma unroll
    for (int mi = 0; mi < 2; mi++)
        #pragma unroll
        for (int ni = 0; ni < 2; ni++) {
            wmma::fill_fragment(acc_s[mi][ni], 0.0f);
            wmma::fill_fragment(acc_l[mi][ni], 0.0f);
        }

    const float4* x4 = reinterpret_cast<const float4*>(x);
    const float4* k4 = reinterpret_cast<const float4*>(keys);
    const float4* u4 = reinterpret_cast<const float4*>(mu);

    for (int k0 = 0; k0 < D_IN; k0 += BK) {
        const int k4off = k0 >> 2;
        // A tile: 128 x 32 = 1024 float4, 4 per thread
        #pragma unroll
        for (int i = 0; i < 4; i++) {
            int j = tid + i * 256;
            int r = j >> 3, c4 = j & 7;
            float4 v = x4[(size_t)(m_base + r) * (D_IN / 4) + k4off + c4];
            float* d = &As[r * A_LD + c4 * 4];
            d[0] = to_tf32(v.x); d[1] = to_tf32(v.y);
            d[2] = to_tf32(v.z); d[3] = to_tf32(v.w);
        }
        // B tiles: 64 x 32 = 512 float4 each, 2 per thread
        #pragma unroll
        for (int i = 0; i < 2; i++) {
            int j = tid + i * 256;
            int r = j >> 3, c4 = j & 7;
            size_t gi = (size_t)(n_base + r) * (D_IN / 4) + k4off + c4;
            float4 vk = k4[gi];
            float* dk = &Bk[r * B_LD + c4 * 4];
            dk[0] = to_tf32(vk.x); dk[1] = to_tf32(vk.y);
            dk[2] = to_tf32(vk.z); dk[3] = to_tf32(vk.w);
            float4 vm = u4[gi];
            float* dm = &Bm[r * B_LD + c4 * 4];
            dm[0] = to_tf32(vm.x); dm[1] = to_tf32(vm.y);
            dm[2] = to_tf32(vm.z); dm[3] = to_tf32(vm.w);
        }
        __syncthreads();

        #pragma unroll
        for (int kk = 0; kk < BK / 8; kk++) {
            wmma::fragment<wmma::matrix_a, 16, 16, 8, wmma::precision::tf32, wmma::row_major> a[2];
            wmma::fragment<wmma::matrix_b, 16, 16, 8, wmma::precision::tf32, wmma::col_major> bk[2], bm[2];
            #pragma unroll
            for (int mi = 0; mi < 2; mi++)
                wmma::load_matrix_sync(a[mi], &As[(wm * 32 + mi * 16) * A_LD + kk * 8], A_LD);
            #pragma unroll
            for (int ni = 0; ni < 2; ni++) {
                wmma::load_matrix_sync(bk[ni], &Bk[(wn * 32 + ni * 16) * B_LD + kk * 8], B_LD);
                wmma::load_matrix_sync(bm[ni], &Bm[(wn * 32 + ni * 16) * B_LD + kk * 8], B_LD);
            }
            #pragma unroll
            for (int mi = 0; mi < 2; mi++)
                #pragma unroll
                for (int ni = 0; ni < 2; ni++) {
                    wmma::mma_sync(acc_s[mi][ni], a[mi], bk[ni], acc_s[mi][ni]);
                    wmma::mma_sync(acc_l[mi][ni], a[mi], bm[ni], acc_l[mi][ni]);
                }
        }
        __syncthreads();
    }

    // Epilogue: stage both accumulators to smem, then fused elementwise + stores.
    float* Ss = smem;                   // [BM][C_LD]
    float* Sl = smem + BM * C_LD;       // [BM][C_LD]
    #pragma unroll
    for (int mi = 0; mi < 2; mi++)
        #pragma unroll
        for (int ni = 0; ni < 2; ni++) {
            wmma::store_matrix_sync(&Ss[(wm * 32 + mi * 16) * C_LD + wn * 32 + ni * 16],
                                    acc_s[mi][ni], C_LD, wmma::mem_row_major);
            wmma::store_matrix_sync(&Sl[(wm * 32 + mi * 16) * C_LD + wn * 32 + ni * 16],
                                    acc_l[mi][ni], C_LD, wmma::mem_row_major);
        }
    __syncthreads();

    const float scale = 0.022097086912079608f;   // 1/sqrt(2048)
    #pragma unroll
    for (int i = 0; i < (BM * BN) / 256; i++) {
        int j = tid + i * 256;
        int r = j >> 6, c = j & 63;
        int o = n_base + c;
        float s = Ss[r * C_LD + c] * scale;
        float lin = Sl[r * C_LD + c];
        float rw = fmaxf(s - gate[o], 0.0f);
        float v = fmaf(rw, lin, bias[o]);
        size_t gi = (size_t)(m_base + r) * D_OUT + o;
        o_final[gi] = v;
        if (o_scores) o_scores[gi] = s;
        if (o_output) o_output[gi] = v;
    }
}

// ---------------------------------------------------------------------------
extern "C" void kernel_launch(void* const* d_in, const int* in_sizes, int n_in,
                              void* d_out, int out_size) {
    const float* x     = (const float*)d_in[0];
    const float* mu    = (const float*)d_in[1];
    const float* sigma = (const float*)d_in[2];
    const float* gate  = (const float*)d_in[3];
    const float* bias  = (const float*)d_in[4];

    float* keys = nullptr;
    cudaGetSymbolAddress((void**)&keys, g_keys);

    const size_t n = (size_t)N_TOK * D_OUT;   // 67108864
    float* out = (float*)d_out;
    float* o_final  = out;
    float* o_scores = nullptr;
    float* o_output = nullptr;
    if ((size_t)out_size >= 3 * n) { o_scores = out + n; o_output = out + 2 * n; }
    else if ((size_t)out_size >= 2 * n) { o_scores = out + n; }

    // 1) keys = mu * softplus(sigma)
    {
        int nk = D_OUT * D_IN;
        int blocks = 4096;
        prep_keys_kernel<<<blocks, 256>>>(mu, sigma, keys, nk);
    }

    // 2) fused dual GEMM + epilogue
    cudaFuncSetAttribute(sbl_gemm_kernel,
                         cudaFuncAttributeMaxDynamicSharedMemorySize, SMEM_BYTES);
    dim3 grid(D_OUT / BN, N_TOK / BM);   // (128, 64)
    sbl_gemm_kernel<<<grid, 256, SMEM_BYTES>>>(x, keys, mu, gate, bias,
                                               o_final, o_scores, o_output);
}

// round 3
// speedup vs baseline: 3.3884x; 3.3884x over previous
#include <cuda_runtime.h>
#include <cuda_fp16.h>
#include <mma.h>
#include <cstdint>

using namespace nvcuda;

// Problem dims (fixed)
#define N_TOK   8192
#define D_IN    2048
#define D_OUT   8192

// Tiling
#define BM      128
#define BN      64
#define BK      32
#define NITER   (D_IN / BK)      // 64
#define STAGES  4

// SMEM layout (halves), padded rows
#define A_LDH   40               // 32 + 8 pad halves
#define B_LDH   40
#define A_STG_B (BM * A_LDH * 2)             // 10240 B
#define B_STG_B (BN * B_LDH * 2)             // 5120 B
#define STG_B   (A_STG_B + 2 * B_STG_B)      // 20480 B
#define SMEM_BYTES (STAGES * STG_B)          // 81920 B

#define C_LD    68               // epilogue floats ld (64+4)

// fp16 scratch (device globals; no allocations)
__device__ __align__(1024) __half g_xh [(size_t)N_TOK * D_IN];
__device__ __align__(1024) __half g_kh [(size_t)D_OUT * D_IN];
__device__ __align__(1024) __half g_mh [(size_t)D_OUT * D_IN];

__device__ __forceinline__ uint32_t smem_u32(const void* p) {
    uint32_t a;
    asm("{ .reg .u64 t; cvta.to.shared.u64 t, %1; cvt.u32.u64 %0, t; }" : "=r"(a) : "l"(p));
    return a;
}
__device__ __forceinline__ void cp16(uint32_t sdst, const void* gsrc) {
    asm volatile("cp.async.cg.shared.global [%0], [%1], 16;" :: "r"(sdst), "l"(gsrc));
}
__device__ __forceinline__ void cp_commit() { asm volatile("cp.async.commit_group;"); }

// ---------------------------------------------------------------------------
// prep kernels: fp32 -> fp16 (keys = mu * softplus(sigma))
// ---------------------------------------------------------------------------
__global__ void prep_keys_h(const float* __restrict__ mu,
                            const float* __restrict__ sigma,
                            __half* __restrict__ keys, int n4) {
    int i = blockIdx.x * blockDim.x + threadIdx.x;
    int stride = gridDim.x * blockDim.x;
    const float4* m4 = (const float4*)mu;
    const float4* s4 = (const float4*)sigma;
    for (; i < n4; i += stride) {
        float4 m = m4[i], s = s4[i];
        float sp;
        __half o[4];
        sp = (s.x > 20.f) ? s.x : log1pf(expf(s.x)); o[0] = __float2half_rn(m.x * sp);
        sp = (s.y > 20.f) ? s.y : log1pf(expf(s.y)); o[1] = __float2half_rn(m.y * sp);
        sp = (s.z > 20.f) ? s.z : log1pf(expf(s.z)); o[2] = __float2half_rn(m.z * sp);
        sp = (s.w > 20.f) ? s.w : log1pf(expf(s.w)); o[3] = __float2half_rn(m.w * sp);
        *reinterpret_cast<uint2*>(keys + 4 * (size_t)i) = *reinterpret_cast<uint2*>(o);
    }
}
__global__ void f2h_kernel(const float* __restrict__ src,
                           __half* __restrict__ dst, int n4) {
    int i = blockIdx.x * blockDim.x + threadIdx.x;
    int stride = gridDim.x * blockDim.x;
    const float4* s4 = (const float4*)src;
    for (; i < n4; i += stride) {
        float4 v = s4[i];
        __half o[4] = { __float2half_rn(v.x), __float2half_rn(v.y),
                        __float2half_rn(v.z), __float2half_rn(v.w) };
        *reinterpret_cast<uint2*>(dst + 4 * (size_t)i) = *reinterpret_cast<uint2*>(o);
    }
}

// ---------------------------------------------------------------------------
// Fused dual GEMM (fp16 WMMA, cp.async 4-stage pipeline) + epilogue
// ---------------------------------------------------------------------------
__global__ void __launch_bounds__(256)
sbl_gemm_h(const __half* __restrict__ gx,
           const __half* __restrict__ gk,
           const __half* __restrict__ gm,
           const float* __restrict__ gate,
           const float* __restrict__ bias,
           float* __restrict__ o_final,
           float* __restrict__ o_scores,
           float* __restrict__ o_output) {
    extern __shared__ char smem[];
    const uint32_t sb = smem_u32(smem);
    const int tid = threadIdx.x;
    const int warp = tid >> 5;
    const int wm = warp & 3;        // M group (32 rows each)
    const int wn = warp >> 2;       // N group (32 cols each)

    // grid swizzle: GROUP_M m-tiles share B panels in L2
    const int num_m = N_TOK / BM;   // 64
    const int num_n = D_OUT / BN;   // 128
    const int GM = 16;
    int pid = blockIdx.x;
    int group = pid / (GM * num_n);
    int first_m = group * GM;
    int gsz = min(num_m - first_m, GM);
    int m_idx = first_m + (pid % gsz);
    int n_idx = (pid % (GM * num_n)) / gsz;
    const int m_base = m_idx * BM;
    const int n_base = n_idx * BN;

    wmma::fragment<wmma::accumulator, 16, 16, 16, float> acc_s[2][2], acc_l[2][2];
    #pragma unroll
    for (int mi = 0; mi < 2; mi++)
        #pragma unroll
        for (int ni = 0; ni < 2; ni++) {
            wmma::fill_fragment(acc_s[mi][ni], 0.0f);
            wmma::fill_fragment(acc_l[mi][ni], 0.0f);
        }

    // per-stage fill: 4 x cp16 per thread (2 for A, 1 for each B)
    auto fill = [&](int stage, int k0) {
        uint32_t st = sb + stage * STG_B;
        #pragma unroll
        for (int j = 0; j < 2; j++) {
            int i = tid + j * 256;
            int r = i >> 2, c = i & 3;          // row 0..127, chunk 0..3 (8 halves)
            cp16(st + r * (A_LDH * 2) + c * 16,
                 gx + (size_t)(m_base + r) * D_IN + k0 + c * 8);
        }
        {
            int r = tid >> 2, c = tid & 3;      // row 0..63
            size_t gi = (size_t)(n_base + r) * D_IN + k0 + c * 8;
            uint32_t so = r * (B_LDH * 2) + c * 16;
            cp16(st + A_STG_B + so, gk + gi);
            cp16(st + A_STG_B + B_STG_B + so, gm + gi);
        }
        cp_commit();
    };

    // prologue: fill stages 0..2
    #pragma unroll
    for (int s = 0; s < STAGES - 1; s++) fill(s, s * BK);

    for (int ks = 0; ks < NITER; ks++) {
        if (ks + STAGES - 1 < NITER) fill((ks + STAGES - 1) & (STAGES - 1),
                                          (ks + STAGES - 1) * BK);
        else cp_commit();                        // keep group accounting
        asm volatile("cp.async.wait_group %0;" :: "n"(STAGES - 1) : "memory");
        __syncthreads();

        const __half* As = (const __half*)(smem + (ks & (STAGES - 1)) * STG_B);
        const __half* Bk = As + BM * A_LDH;
        const __half* Bm = Bk + BN * B_LDH;

        #pragma unroll
        for (int kk = 0; kk < BK / 16; kk++) {
            wmma::fragment<wmma::matrix_a, 16, 16, 16, __half, wmma::row_major> a[2];
            wmma::fragment<wmma::matrix_b, 16, 16, 16, __half, wmma::col_major> bk[2], bm[2];
            #pragma unroll
            for (int mi = 0; mi < 2; mi++)
                wmma::load_matrix_sync(a[mi], &As[(wm * 32 + mi * 16) * A_LDH + kk * 16], A_LDH);
            #pragma unroll
            for (int ni = 0; ni < 2; ni++) {
                wmma::load_matrix_sync(bk[ni], &Bk[(wn * 32 + ni * 16) * B_LDH + kk * 16], B_LDH);
                wmma::load_matrix_sync(bm[ni], &Bm[(wn * 32 + ni * 16) * B_LDH + kk * 16], B_LDH);
            }
            #pragma unroll
            for (int mi = 0; mi < 2; mi++)
                #pragma unroll
                for (int ni = 0; ni < 2; ni++) {
                    wmma::mma_sync(acc_s[mi][ni], a[mi], bk[ni], acc_s[mi][ni]);
                    wmma::mma_sync(acc_l[mi][ni], a[mi], bm[ni], acc_l[mi][ni]);
                }
        }
        __syncthreads();
    }

    // epilogue: stage to smem, fused elementwise, vectorized stores
    float* Ss = (float*)smem;                 // [BM][C_LD]
    float* Sl = Ss + BM * C_LD;
    #pragma unroll
    for (int mi = 0; mi < 2; mi++)
        #pragma unroll
        for (int ni = 0; ni < 2; ni++) {
            wmma::store_matrix_sync(&Ss[(wm * 32 + mi * 16) * C_LD + wn * 32 + ni * 16],
                                    acc_s[mi][ni], C_LD, wmma::mem_row_major);
            wmma::store_matrix_sync(&Sl[(wm * 32 + mi * 16) * C_LD + wn * 32 + ni * 16],
                                    acc_l[mi][ni], C_LD, wmma::mem_row_major);
        }
    __syncthreads();

    const float scale = 0.022097086912079608f;   // 1/sqrt(2048)
    #pragma unroll
    for (int i = 0; i < (BM * BN) / (256 * 4); i++) {   // 8 iters, 4 cols/thread
        int j = tid + i * 256;
        int r = j >> 4, c4 = (j & 15) * 4;
        int o = n_base + c4;
        float sv[4], vv[4];
        #pragma unroll
        for (int q = 0; q < 4; q++) {
            float s = Ss[r * C_LD + c4 + q] * scale;
            float rw = fmaxf(s - __ldg(&gate[o + q]), 0.0f);
            sv[q] = s;
            vv[q] = fmaf(rw, Sl[r * C_LD + c4 + q], __ldg(&bias[o + q]));
        }
        size_t gi = (size_t)(m_base + r) * D_OUT + o;
        *reinterpret_cast<float4*>(o_final + gi) = make_float4(vv[0], vv[1], vv[2], vv[3]);
        if (o_output)
            *reinterpret_cast<float4*>(o_output + gi) = make_float4(vv[0], vv[1], vv[2], vv[3]);
        if (o_scores)
            *reinterpret_cast<float4*>(o_scores + gi) = make_float4(sv[0], sv[1], sv[2], sv[3]);
    }
}

// ---------------------------------------------------------------------------
extern "C" void kernel_launch(void* const* d_in, const int* in_sizes, int n_in,
                              void* d_out, int out_size) {
    const float* x     = (const float*)d_in[0];
    const float* mu    = (const float*)d_in[1];
    const float* sigma = (const float*)d_in[2];
    const float* gate  = (const float*)d_in[3];
    const float* bias  = (const float*)d_in[4];

    __half *xh, *kh, *mh;
    cudaGetSymbolAddress((void**)&xh, g_xh);
    cudaGetSymbolAddress((void**)&kh, g_kh);
    cudaGetSymbolAddress((void**)&mh, g_mh);

    const size_t n = (size_t)N_TOK * D_OUT;
    float* out = (float*)d_out;
    float* o_final  = out;
    float* o_scores = nullptr;
    float* o_output = nullptr;
    if ((size_t)out_size >= 3 * n)      { o_scores = out + n; o_output = out + 2 * n; }
    else if ((size_t)out_size >= 2 * n) { o_scores = out + n; }

    f2h_kernel<<<2048, 256>>>(x, xh, (N_TOK * D_IN) / 4);
    f2h_kernel<<<2048, 256>>>(mu, mh, (D_OUT * D_IN) / 4);
    prep_keys_h<<<2048, 256>>>(mu, sigma, kh, (D_OUT * D_IN) / 4);

    cudaFuncSetAttribute(sbl_gemm_h,
                         cudaFuncAttributeMaxDynamicSharedMemorySize, SMEM_BYTES);
    dim3 grid((N_TOK / BM) * (D_OUT / BN));   // 8192 CTAs
    sbl_gemm_h<<<grid, 256, SMEM_BYTES>>>(xh, kh, mh, gate, bias,
                                          o_final, o_scores, o_output);
}

// round 4
// speedup vs baseline: 3.8638x; 1.1403x over previous
#include <cuda_runtime.h>
#include <cuda_fp16.h>
#include <cstdint>

// Problem dims (fixed)
#define N_TOK   8192
#define D_IN    2048
#define D_OUT   8192

// Tiling
#define BM      128
#define BN      128
#define BK      32
#define NITER   (D_IN / BK)          // 64
#define STAGES  4

#define A_BYTES 8192                 // 128 rows * 32 halves * 2B
#define B_BYTES 8192                 // per B operand
#define STG_B   (A_BYTES + 2 * B_BYTES)    // 24576
#define SMEM_BYTES (STAGES * STG_B)        // 98304

// fp16 scratch (device globals; no allocations)
__device__ __align__(1024) __half g_xh [(size_t)N_TOK * D_IN];
__device__ __align__(1024) __half g_kh [(size_t)D_OUT * D_IN];
__device__ __align__(1024) __half g_mh [(size_t)D_OUT * D_IN];

__device__ __forceinline__ uint32_t smem_u32(const void* p) {
    uint32_t a;
    asm("{ .reg .u64 t; cvta.to.shared.u64 t, %1; cvt.u32.u64 %0, t; }" : "=r"(a) : "l"(p));
    return a;
}
__device__ __forceinline__ uint32_t swz(uint32_t off) {   // 128B XOR swizzle
    return off ^ ((off >> 3) & 0x70);
}
__device__ __forceinline__ void cp16(uint32_t sdst, const void* gsrc) {
    asm volatile("cp.async.cg.shared.global [%0], [%1], 16;" :: "r"(sdst), "l"(gsrc));
}
__device__ __forceinline__ void cp_commit() { asm volatile("cp.async.commit_group;"); }

__device__ __forceinline__ void ldsm4(uint32_t* r, uint32_t addr) {
    asm volatile("ldmatrix.sync.aligned.m8n8.x4.shared.b16 {%0,%1,%2,%3}, [%4];"
                 : "=r"(r[0]), "=r"(r[1]), "=r"(r[2]), "=r"(r[3]) : "r"(addr));
}
__device__ __forceinline__ void mma16816(float* c, const uint32_t* a,
                                         uint32_t b0, uint32_t b1) {
    asm volatile(
        "mma.sync.aligned.m16n8k16.row.col.f32.f16.f16.f32 "
        "{%0,%1,%2,%3}, {%4,%5,%6,%7}, {%8,%9}, {%0,%1,%2,%3};"
        : "+f"(c[0]), "+f"(c[1]), "+f"(c[2]), "+f"(c[3])
        : "r"(a[0]), "r"(a[1]), "r"(a[2]), "r"(a[3]), "r"(b0), "r"(b1));
}

// ---------------------------------------------------------------------------
// prep kernels: fp32 -> fp16 (keys = mu * softplus(sigma))
// ---------------------------------------------------------------------------
__global__ void prep_keys_h(const float* __restrict__ mu,
                            const float* __restrict__ sigma,
                            __half* __restrict__ keys, int n4) {
    int i = blockIdx.x * blockDim.x + threadIdx.x;
    int stride = gridDim.x * blockDim.x;
    const float4* m4 = (const float4*)mu;
    const float4* s4 = (const float4*)sigma;
    for (; i < n4; i += stride) {
        float4 m = m4[i], s = s4[i];
        float sp;
        __half o[4];
        sp = (s.x > 20.f) ? s.x : log1pf(expf(s.x)); o[0] = __float2half_rn(m.x * sp);
        sp = (s.y > 20.f) ? s.y : log1pf(expf(s.y)); o[1] = __float2half_rn(m.y * sp);
        sp = (s.z > 20.f) ? s.z : log1pf(expf(s.z)); o[2] = __float2half_rn(m.z * sp);
        sp = (s.w > 20.f) ? s.w : log1pf(expf(s.w)); o[3] = __float2half_rn(m.w * sp);
        *reinterpret_cast<uint2*>(keys + 4 * (size_t)i) = *reinterpret_cast<uint2*>(o);
    }
}
__global__ void f2h_kernel(const float* __restrict__ src,
                           __half* __restrict__ dst, int n4) {
    int i = blockIdx.x * blockDim.x + threadIdx.x;
    int stride = gridDim.x * blockDim.x;
    const float4* s4 = (const float4*)src;
    for (; i < n4; i += stride) {
        float4 v = s4[i];
        __half o[4] = { __float2half_rn(v.x), __float2half_rn(v.y),
                        __float2half_rn(v.z), __float2half_rn(v.w) };
        *reinterpret_cast<uint2*>(dst + 4 * (size_t)i) = *reinterpret_cast<uint2*>(o);
    }
}

// ---------------------------------------------------------------------------
// Fused dual GEMM: mma.m16n8k16 + ldmatrix, 4-stage cp.async, reg epilogue
// 8 warps: wm = warp>>2 (M 64-row half), wn = warp&3 (N 32-col quarter)
// ---------------------------------------------------------------------------
__global__ void __launch_bounds__(256, 1)
sbl_gemm_mma(const __half* __restrict__ gx,
             const __half* __restrict__ gk,
             const __half* __restrict__ gm,
             const float* __restrict__ gate,
             const float* __restrict__ bias,
             float* __restrict__ o_final,
             float* __restrict__ o_scores,
             float* __restrict__ o_output) {
    extern __shared__ char smem[];
    const uint32_t sb = smem_u32(smem);
    const int tid = threadIdx.x;
    const int warp = tid >> 5;
    const int lane = tid & 31;
    const int wm = warp >> 2;        // 0..1
    const int wn = warp & 3;         // 0..3

    // grid rasterization: GM=8 m-tiles grouped per n column sweep (L2 reuse)
    const int num_n = D_OUT / BN;    // 64
    const int GM = 8;
    int pid = blockIdx.x;
    int group = pid / (GM * num_n);
    int within = pid % (GM * num_n);
    const int m_base = (group * GM + (within % GM)) * BM;
    const int n_base = (within / GM) * BN;

    float acc_s[4][4][4], acc_l[4][4][4];
    #pragma unroll
    for (int a = 0; a < 4; a++)
        #pragma unroll
        for (int b = 0; b < 4; b++)
            #pragma unroll
            for (int c = 0; c < 4; c++) { acc_s[a][b][c] = 0.f; acc_l[a][b][c] = 0.f; }

    // stage fill: A 512 chunks, B 2x512 chunks, 16B each; 256 threads
    auto fill = [&](int stage, int k0) {
        uint32_t st = sb + stage * STG_B;
        #pragma unroll
        for (int j = 0; j < 2; j++) {
            int id = tid + j * 256;
            int r = id >> 2, c = id & 3;
            cp16(st + swz(r * 64 + c * 16),
                 gx + (size_t)(m_base + r) * D_IN + k0 + c * 8);
        }
        #pragma unroll
        for (int j = 0; j < 2; j++) {
            int id = tid + j * 256;
            int r = id >> 2, c = id & 3;
            uint32_t so = swz(r * 64 + c * 16);
            size_t gi = (size_t)(n_base + r) * D_IN + k0 + c * 8;
            cp16(st + A_BYTES + so, gk + gi);
            cp16(st + A_BYTES + B_BYTES + so, gm + gi);
        }
        cp_commit();
    };

    #pragma unroll
    for (int s = 0; s < STAGES - 1; s++) fill(s, s * BK);

    const int lr = lane & 15;        // ldsm row within 16
    const int lc = lane >> 4;        // ldsm chunk select (0/1)

    for (int ks = 0; ks < NITER; ks++) {
        asm volatile("cp.async.wait_group 2;" ::: "memory");
        __syncthreads();
        if (ks + STAGES - 1 < NITER) fill((ks + STAGES - 1) & 3, (ks + STAGES - 1) * BK);
        else cp_commit();

        const uint32_t st = sb + (ks & 3) * STG_B;

        #pragma unroll
        for (int kk = 0; kk < 2; kk++) {
            const int cch = 2 * kk + lc;
            uint32_t afr[4][4];
            #pragma unroll
            for (int mf = 0; mf < 4; mf++) {
                int r = wm * 64 + mf * 16 + lr;
                ldsm4(afr[mf], st + swz(r * 64 + cch * 16));
            }
            uint32_t bkf[2][4], bmf[2][4];
            #pragma unroll
            for (int g = 0; g < 2; g++) {
                int r = wn * 32 + g * 16 + lr;
                uint32_t off = swz(r * 64 + cch * 16);
                ldsm4(bkf[g], st + A_BYTES + off);
                ldsm4(bmf[g], st + A_BYTES + B_BYTES + off);
            }
            #pragma unroll
            for (int mf = 0; mf < 4; mf++)
                #pragma unroll
                for (int nf = 0; nf < 4; nf++) {
                    const int g = nf >> 1, sel = nf & 1;
                    mma16816(acc_s[mf][nf], afr[mf], bkf[g][sel], bkf[g][sel + 2]);
                    mma16816(acc_l[mf][nf], afr[mf], bmf[g][sel], bmf[g][sel + 2]);
                }
        }
    }

    // ---- register epilogue: fuse scale/relu-gate/bias, float2 stores ----
    const float scale = 0.022097086912079608f;   // 1/sqrt(2048)
    const int r0base = m_base + wm * 64 + (lane >> 2);
    const int cbase  = n_base + wn * 32 + (lane & 3) * 2;

    #pragma unroll
    for (int mf = 0; mf < 4; mf++) {
        const int r0 = r0base + mf * 16;
        #pragma unroll
        for (int nf = 0; nf < 4; nf++) {
            const int c = cbase + nf * 8;
            const float2 gt = *reinterpret_cast<const float2*>(gate + c);
            const float2 bs = *reinterpret_cast<const float2*>(bias + c);
            float s0 = acc_s[mf][nf][0] * scale;
            float s1 = acc_s[mf][nf][1] * scale;
            float s2 = acc_s[mf][nf][2] * scale;
            float s3 = acc_s[mf][nf][3] * scale;
            float v0 = fmaf(fmaxf(s0 - gt.x, 0.f), acc_l[mf][nf][0], bs.x);
            float v1 = fmaf(fmaxf(s1 - gt.y, 0.f), acc_l[mf][nf][1], bs.y);
            float v2 = fmaf(fmaxf(s2 - gt.x, 0.f), acc_l[mf][nf][2], bs.x);
            float v3 = fmaf(fmaxf(s3 - gt.y, 0.f), acc_l[mf][nf][3], bs.y);
            size_t o0 = (size_t)r0 * D_OUT + c;
            size_t o1 = (size_t)(r0 + 8) * D_OUT + c;
            *reinterpret_cast<float2*>(o_final + o0) = make_float2(v0, v1);
            *reinterpret_cast<float2*>(o_final + o1) = make_float2(v2, v3);
            if (o_scores) {
                *reinterpret_cast<float2*>(o_scores + o0) = make_float2(s0, s1);
                *reinterpret_cast<float2*>(o_scores + o1) = make_float2(s2, s3);
            }
            if (o_output) {
                *reinterpret_cast<float2*>(o_output + o0) = make_float2(v0, v1);
                *reinterpret_cast<float2*>(o_output + o1) = make_float2(v2, v3);
            }
        }
    }
}

// ---------------------------------------------------------------------------
extern "C" void kernel_launch(void* const* d_in, const int* in_sizes, int n_in,
                              void* d_out, int out_size) {
    const float* x     = (const float*)d_in[0];
    const float* mu    = (const float*)d_in[1];
    const float* sigma = (const float*)d_in[2];
    const float* gate  = (const float*)d_in[3];
    const float* bias  = (const float*)d_in[4];

    __half *xh, *kh, *mh;
    cudaGetSymbolAddress((void**)&xh, g_xh);
    cudaGetSymbolAddress((void**)&kh, g_kh);
    cudaGetSymbolAddress((void**)&mh, g_mh);

    const size_t n = (size_t)N_TOK * D_OUT;
    float* out = (float*)d_out;
    float* o_final  = out;
    float* o_scores = nullptr;
    float* o_output = nullptr;
    if ((size_t)out_size >= 3 * n)      { o_scores = out + n; o_output = out + 2 * n; }
    else if ((size_t)out_size >= 2 * n) { o_scores = out + n; }

    f2h_kernel<<<2048, 256>>>(x, xh, (N_TOK * D_IN) / 4);
    f2h_kernel<<<2048, 256>>>(mu, mh, (D_OUT * D_IN) / 4);
    prep_keys_h<<<2048, 256>>>(mu, sigma, kh, (D_OUT * D_IN) / 4);

    cudaFuncSetAttribute(sbl_gemm_mma,
                         cudaFuncAttributeMaxDynamicSharedMemorySize, SMEM_BYTES);
    dim3 grid((N_TOK / BM) * (D_OUT / BN));   // 4096 CTAs
    sbl_gemm_mma<<<grid, 256, SMEM_BYTES>>>(xh, kh, mh, gate, bias,
                                            o_final, o_scores, o_output);
}